// round 12
// baseline (speedup 1.0000x reference)
#include <cuda_runtime.h>
#include <cuda_fp16.h>
#include <cstdint>

// ---------------- problem dims ----------------
constexpr int Bc   = 128;     // batch
constexpr int Nf   = 196;     // spatial features
constexpr int ENC  = 512;
constexpr int AD   = 512;     // attention dim
constexpr int DD   = 512;     // decoder dim
constexpr int ED   = 300;     // embed dim
constexpr int VV   = 10000;   // vocab
constexpr int LL   = 25;
constexpr int TT   = 24;      // L-1
constexpr int KCAT = ED + ENC + DD;   // 1324
constexpr int G4   = 4 * DD;          // 2048 (gate-interleaved: col = 4d+g)
constexpr int KS   = 8;               // split-K for gates GEMM
constexpr int GCHUNK = 168;           // 1324/8 rounded (mult of 4)
constexpr int DPS  = 8;               // split-K for dec_proj (+LSTM prologue)
constexpr int DPCHUNK = 64;
constexpr int PBATCH = 6;             // preds steps per side-stream batch

// ---------------- device scratch (static; no runtime alloc) ----------------
__device__ __half g_featproj_h[Bc * Nf * AD];     // 25.7 MB (fp16 feat_proj)
__device__ float g_Wcat[KCAT * G4];               // 10.9 MB (gate-interleaved col=4d+g)
__device__ float g_bcat[G4];
__device__ float g_meanf[Bc * ENC];
__device__ float g_c[2][Bc * DD];                 // ping-pong cell state
__device__ float g_dppart[DPS * Bc * AD];         // dec_proj split-K partials (2 MB)
__device__ float g_xcat[TT * Bc * KCAT];          // 16.3 MB  [t][b][emb|ctx|h]
__device__ float g_gpart[KS * Bc * G4];           // 8 MB gates split-K partials
__device__ float g_Hall[TT * Bc * DD];            // 6.3 MB

// ================= TF32 tensor-core GEMM (unified) =================
// MODE 0: C[m*ldc+n] (+bias); OUTH: write __half
// MODE 1: m=t*128+b (t local) -> C[(b*TT + t0 + t)*ldc+n] + bias  (preds remap)
// MODE 2: split-K partial: K range [z*kchunk, ...), C += z*M*ldc, no bias
// MODE 6: MODE 2 + LSTM prologue for step t0 (if t0>=0): this CTA computes h for
//         its own K-slice (d in [kbeg,kend)) for all batches, writes c/Hall/xcat,
//         then GEMMs with A = the just-written h rows.  (dec_proj kernel)
__device__ __forceinline__ uint32_t f2tf(float x) {
    uint32_t r; asm("cvt.rna.tf32.f32 %0, %1;" : "=r"(r) : "f"(x)); return r;
}
__device__ __forceinline__ void mma8(float* c, const uint32_t* a, const uint32_t* b) {
    asm volatile("mma.sync.aligned.m16n8k8.row.col.f32.tf32.tf32.f32 "
                 "{%0,%1,%2,%3},{%4,%5,%6,%7},{%8,%9},{%0,%1,%2,%3};"
                 : "+f"(c[0]), "+f"(c[1]), "+f"(c[2]), "+f"(c[3])
                 : "r"(a[0]), "r"(a[1]), "r"(a[2]), "r"(a[3]), "r"(b[0]), "r"(b[1]));
}

template<int MODE, bool OUTH>
__global__ __launch_bounds__(256)
void gemm_tc(const float* __restrict__ A, int lda,
             const float* __restrict__ B, int ldb,
             const float* __restrict__ bias, float* __restrict__ C, int ldc,
             int M, int N, int K, int kchunk, int t0)
{
    constexpr int ASTR = 36;
    constexpr int BSTR = 136;
    __shared__ float As[128 * ASTR];   // [m][k]
    __shared__ float Bs[32 * BSTR];    // [k][n]

    const int tid  = threadIdx.x;
    const int lane = tid & 31, warp = tid >> 5;
    const int wm = (warp >> 2) * 64;
    const int wn = (warp & 3) * 32;
    const int l4 = lane >> 2, lq = lane & 3;
    const int row0 = blockIdx.y * 128;
    const int col0 = blockIdx.x * 128;
    const int kbeg = (MODE == 2 || MODE == 6) ? blockIdx.z * kchunk : 0;
    const int kend = (MODE == 2 || MODE == 6) ? min(K, kbeg + kchunk) : K;

    // ---- MODE 6 prologue: LSTM for step t0 over this CTA's K-slice ----
    if (MODE == 6 && t0 >= 0) {
        const int csrc = t0 & 1, cdst = csrc ^ 1;
        const float4* bc4 = reinterpret_cast<const float4*>(g_bcat);
        const float4* gp4 = reinterpret_cast<const float4*>(g_gpart);
        const int nloc = kend - kbeg;                 // 64
        for (int u = tid; u < Bc * nloc; u += 256) {
            int b = u / nloc;
            int d = kbeg + (u - b * nloc);
            float4 g = bc4[d];
#pragma unroll
            for (int z = 0; z < KS; z++) {
                float4 p = gp4[((size_t)(z * Bc + b) * G4 >> 2) + d];
                g.x += p.x; g.y += p.y; g.z += p.z; g.w += p.w;
            }
            float si = 1.f / (1.f + expf(-g.x));
            float sf = 1.f / (1.f + expf(-g.y));
            float so = 1.f / (1.f + expf(-g.w));
            float cn = sf * g_c[csrc][b * DD + d] + si * tanhf(g.z);
            float hn = so * tanhf(cn);
            g_c[cdst][b * DD + d] = cn;
            g_Hall[((size_t)t0 * Bc + b) * DD + d] = hn;
            g_xcat[((size_t)(t0 + 1) * Bc + b) * KCAT + ED + ENC + d] = hn;
        }
        __syncthreads();   // h slice visible to this CTA's A-tile loads
    }

    float acc[4][4][4];
#pragma unroll
    for (int i = 0; i < 4; i++)
#pragma unroll
        for (int j = 0; j < 4; j++)
#pragma unroll
            for (int q = 0; q < 4; q++) acc[i][j][q] = 0.f;

    const uint32_t* Asu = reinterpret_cast<const uint32_t*>(As);
    const uint32_t* Bsu = reinterpret_cast<const uint32_t*>(Bs);

    float4 pa[4], pb[4];
    auto ldA = [&](int kt) {
#pragma unroll
        for (int i = 0; i < 4; i++) {
            int l = tid + i * 256;
            int m = l >> 3, kq = (l & 7) << 2;
            int gk = kt + kq;
            pa[i] = make_float4(0.f, 0.f, 0.f, 0.f);
            if (gk < kend)
                pa[i] = *reinterpret_cast<const float4*>(A + (size_t)(row0 + m) * lda + gk);
        }
    };
    auto ldB = [&](int kt) {
#pragma unroll
        for (int i = 0; i < 4; i++) {
            int l = tid + i * 256;
            int k = l >> 5, nq = (l & 31) << 2;
            int gk = kt + k, gn = col0 + nq;
            pb[i] = make_float4(0.f, 0.f, 0.f, 0.f);
            if (gk < kend && gn < N)
                pb[i] = *reinterpret_cast<const float4*>(B + (size_t)gk * ldb + gn);
        }
    };

    ldA(kbeg); ldB(kbeg);
    for (int kt = kbeg; kt < kend; kt += 32) {
#pragma unroll
        for (int i = 0; i < 4; i++) {
            int l = tid + i * 256;
            int m = l >> 3, kq = (l & 7) << 2;
            uint4 u = make_uint4(f2tf(pa[i].x), f2tf(pa[i].y), f2tf(pa[i].z), f2tf(pa[i].w));
            *reinterpret_cast<uint4*>(As + m * ASTR + kq) = u;
        }
#pragma unroll
        for (int i = 0; i < 4; i++) {
            int l = tid + i * 256;
            int k = l >> 5, nq = (l & 31) << 2;
            uint4 u = make_uint4(f2tf(pb[i].x), f2tf(pb[i].y), f2tf(pb[i].z), f2tf(pb[i].w));
            *reinterpret_cast<uint4*>(Bs + k * BSTR + nq) = u;
        }
        __syncthreads();
        if (kt + 32 < kend) { ldA(kt + 32); ldB(kt + 32); }
#pragma unroll
        for (int kk = 0; kk < 32; kk += 8) {
            uint32_t af[4][4], bf[4][2];
#pragma unroll
            for (int mi = 0; mi < 4; mi++) {
                int r = wm + 16 * mi + l4;
                af[mi][0] = Asu[r * ASTR + kk + lq];
                af[mi][1] = Asu[(r + 8) * ASTR + kk + lq];
                af[mi][2] = Asu[r * ASTR + kk + lq + 4];
                af[mi][3] = Asu[(r + 8) * ASTR + kk + lq + 4];
            }
#pragma unroll
            for (int ni = 0; ni < 4; ni++) {
                int c = wn + 8 * ni + l4;
                bf[ni][0] = Bsu[(kk + lq) * BSTR + c];
                bf[ni][1] = Bsu[(kk + lq + 4) * BSTR + c];
            }
#pragma unroll
            for (int mi = 0; mi < 4; mi++)
#pragma unroll
                for (int ni = 0; ni < 4; ni++)
                    mma8(acc[mi][ni], af[mi], bf[ni]);
        }
        __syncthreads();
    }

    float* Cb = (MODE == 2 || MODE == 6) ? (C + (size_t)blockIdx.z * M * ldc) : C;
#pragma unroll
    for (int mi = 0; mi < 4; mi++) {
#pragma unroll
        for (int ni = 0; ni < 4; ni++) {
            int r = row0 + wm + 16 * mi + l4;
            int c = col0 + wn + 8 * ni + 2 * lq;
#pragma unroll
            for (int half = 0; half < 2; half++) {
                int rr = r + half * 8;
                size_t rowidx;
                if (MODE == 1) { int t = (rr >> 7) + t0, b = rr & 127; rowidx = (size_t)(b * TT + t); }
                else rowidx = (size_t)rr;
#pragma unroll
                for (int jj = 0; jj < 2; jj++) {
                    int cc = c + jj;
                    if (cc < N) {
                        float v = acc[mi][ni][half * 2 + jj];
                        if (MODE == 0 || MODE == 1) { if (bias) v += bias[cc]; }
                        if (OUTH)
                            reinterpret_cast<__half*>(Cb)[rowidx * ldc + cc] = __float2half_rn(v);
                        else
                            Cb[rowidx * ldc + cc] = v;
                    }
                }
            }
        }
    }
}

// ================= fp32 GEMM (h0/c0 only; exact, run once) =================
template<int BM, int BN, int BK, int TM, int TN>
__global__ void gemm_f32(const float* __restrict__ A, int lda,
                         const float* __restrict__ B, int ldb,
                         const float* __restrict__ bias, float* __restrict__ C, int ldc,
                         int M, int N, int K)
{
    constexpr int THREADS = (BM / TM) * (BN / TN);
    constexpr int AF4 = BM * BK / 4 / THREADS;
    constexpr int BF4 = BK * BN / 4 / THREADS;
    __shared__ float As[BK][BM];
    __shared__ float Bs[BK][BN];
    const int tid = threadIdx.x;
    const int tx = tid % (BN / TN), ty = tid / (BN / TN);
    const int row0 = blockIdx.y * BM, col0 = blockIdx.x * BN;

    float acc[TM][TN];
#pragma unroll
    for (int i = 0; i < TM; i++)
#pragma unroll
        for (int j = 0; j < TN; j++) acc[i][j] = 0.f;

    float4 pa[AF4], pb[BF4];
    auto load_regs = [&](int kt) {
#pragma unroll
        for (int i = 0; i < AF4; i++) {
            int l = tid + i * THREADS;
            int m = l / (BK / 4), kq = (l % (BK / 4)) * 4;
            pa[i] = *reinterpret_cast<const float4*>(A + (size_t)(row0 + m) * lda + kt + kq);
        }
#pragma unroll
        for (int i = 0; i < BF4; i++) {
            int l = tid + i * THREADS;
            int k = l / (BN / 4), nq = (l % (BN / 4)) * 4;
            pb[i] = *reinterpret_cast<const float4*>(B + (size_t)(kt + k) * ldb + col0 + nq);
        }
    };
    load_regs(0);
    for (int kt = 0; kt < K; kt += BK) {
#pragma unroll
        for (int i = 0; i < AF4; i++) {
            int l = tid + i * THREADS;
            int m = l / (BK / 4), kq = (l % (BK / 4)) * 4;
            As[kq + 0][m] = pa[i].x; As[kq + 1][m] = pa[i].y;
            As[kq + 2][m] = pa[i].z; As[kq + 3][m] = pa[i].w;
        }
#pragma unroll
        for (int i = 0; i < BF4; i++) {
            int l = tid + i * THREADS;
            int k = l / (BN / 4), nq = (l % (BN / 4)) * 4;
            *reinterpret_cast<float4*>(&Bs[k][nq]) = pb[i];
        }
        __syncthreads();
        if (kt + BK < K) load_regs(kt + BK);
#pragma unroll
        for (int kk = 0; kk < BK; kk++) {
            float ra[TM], rb[TN];
#pragma unroll
            for (int i = 0; i < TM; i += 4)
                *reinterpret_cast<float4*>(&ra[i]) =
                    *reinterpret_cast<const float4*>(&As[kk][ty * TM + i]);
#pragma unroll
            for (int j = 0; j < TN; j += 4)
                *reinterpret_cast<float4*>(&rb[j]) =
                    *reinterpret_cast<const float4*>(&Bs[kk][tx * TN + j]);
#pragma unroll
            for (int i = 0; i < TM; i++)
#pragma unroll
                for (int j = 0; j < TN; j++)
                    acc[i][j] = fmaf(ra[i], rb[j], acc[i][j]);
        }
        __syncthreads();
    }
#pragma unroll
    for (int i = 0; i < TM; i++) {
        int m = row0 + ty * TM + i;
#pragma unroll
        for (int j = 0; j < TN; j += 4) {
            int n = col0 + tx * TN + j;
            float4 v = make_float4(acc[i][j] + bias[n], acc[i][j + 1] + bias[n + 1],
                                   acc[i][j + 2] + bias[n + 2], acc[i][j + 3] + bias[n + 3]);
            *reinterpret_cast<float4*>(C + (size_t)m * ldc + n) = v;
        }
    }
}

// ---------------- setup kernels ----------------
__global__ void wcat_kernel(const float* __restrict__ Wih, const float* __restrict__ Whh,
                            const float* __restrict__ bih, const float* __restrict__ bhh)
{
    int idx = blockIdx.x * blockDim.x + threadIdx.x;
    if (idx >= KCAT * G4) return;
    int k = idx / G4, n = idx - k * G4;
    int d = n >> 2, g = n & 3;
    int col = g * DD + d;
    float v = (k < ED + ENC) ? Wih[(size_t)k * G4 + col]
                             : Whh[(size_t)(k - ED - ENC) * G4 + col];
    g_Wcat[idx] = v;
    if (idx < G4) {
        int dd = idx >> 2, gg = idx & 3;
        int c2 = gg * DD + dd;
        g_bcat[idx] = bih[c2] + bhh[c2];
    }
}

__global__ void meanf_kernel(const float* __restrict__ feat)
{
    int idx = blockIdx.x * blockDim.x + threadIdx.x;
    if (idx >= Bc * ENC) return;
    int b = idx >> 9, d = idx & 511;
    const float* p = feat + (size_t)b * Nf * ENC + d;
    float s = 0.f;
#pragma unroll 4
    for (int n = 0; n < Nf; n++) s += p[(size_t)n * ENC];
    g_meanf[idx] = s * (1.f / (float)Nf);
}

__global__ void embfill_kernel(const int* __restrict__ captions, const float* __restrict__ emb)
{
    int idx = blockIdx.x * blockDim.x + threadIdx.x;
    if (idx >= TT * Bc * ED) return;
    int t = idx / (Bc * ED);
    int r = idx - t * (Bc * ED);
    int b = r / ED, j = r - b * ED;
    int tok = captions[b * LL + t];
    g_xcat[((size_t)t * Bc + b) * KCAT + j] = emb[(size_t)tok * ED + j];
}

// ---------------- fused attention (dec_proj reduce + fp16 featproj + MUFU) ---------
__global__ __launch_bounds__(512)
void attn_kernel(const float* __restrict__ features, const float* __restrict__ w_att,
                 const float* __restrict__ b_dec, float* __restrict__ alpha_out, int t)
{
    __shared__ float decp[AD];
    __shared__ float watt[AD];
    __shared__ float al[Nf];
    __shared__ float red[256];
    const int b = blockIdx.x, tid = threadIdx.x;
    {
        float s = b_dec[tid];
#pragma unroll
        for (int z = 0; z < DPS; z++)
            s += g_dppart[((size_t)z * Bc + b) * AD + tid];
        decp[tid] = s;
    }
    watt[tid] = w_att[tid];
    __syncthreads();

    const int warp = tid >> 5, lane = tid & 31;
    for (int n = warp; n < Nf; n += 16) {
        const __half* fp = g_featproj_h + ((size_t)b * Nf + n) * AD;
        float s = 0.f;
#pragma unroll
        for (int a = lane * 2; a < AD; a += 64) {
            __half2 h2 = *reinterpret_cast<const __half2*>(fp + a);
            float2 f2 = __half22float2(h2);
            float t0, t1;
            asm("tanh.approx.f32 %0, %1;" : "=f"(t0) : "f"(f2.x + decp[a]));
            asm("tanh.approx.f32 %0, %1;" : "=f"(t1) : "f"(f2.y + decp[a + 1]));
            s += t0 * watt[a] + t1 * watt[a + 1];
        }
#pragma unroll
        for (int o = 16; o; o >>= 1) s += __shfl_xor_sync(0xFFFFFFFFu, s, o);
        if (lane == 0) al[n] = s;
    }
    __syncthreads();

    if (tid < 256) red[tid] = (tid < Nf) ? al[tid] : -1e30f;
    __syncthreads();
    for (int s = 128; s; s >>= 1) { if (tid < s) red[tid] = fmaxf(red[tid], red[tid + s]); __syncthreads(); }
    float mx = red[0];
    __syncthreads();
    float e = (tid < Nf) ? __expf(al[tid] - mx) : 0.f;
    if (tid < 256) red[tid] = e;
    __syncthreads();
    for (int s = 128; s; s >>= 1) { if (tid < s) red[tid] += red[tid + s]; __syncthreads(); }
    float inv = 1.f / red[0];
    if (tid < Nf) {
        float a = e * inv;
        al[tid] = a;
        if (alpha_out) alpha_out[(size_t)(b * TT + t) * Nf + tid] = a;
    }
    __syncthreads();

    const float* fb = features + (size_t)b * Nf * ENC;
    float s = 0.f;
#pragma unroll 4
    for (int n = 0; n < Nf; n++) s += al[n] * fb[(size_t)n * ENC + tid];
    g_xcat[((size_t)t * Bc + b) * KCAT + ED + tid] = s;
}

// ---------------- split-K reduce + LSTM pointwise (final step only) ----------------
__global__ void lstm_reduce(int t)
{
    int idx = blockIdx.x * blockDim.x + threadIdx.x;
    if (idx >= Bc * DD) return;
    int b = idx >> 9, d = idx & 511;
    const int csrc = t & 1, cdst = csrc ^ 1;
    float4 g = reinterpret_cast<const float4*>(g_bcat)[d];
    const float4* gp = reinterpret_cast<const float4*>(g_gpart);
#pragma unroll
    for (int ks = 0; ks < KS; ks++) {
        float4 p = gp[((size_t)(ks * Bc + b) * G4 >> 2) + d];
        g.x += p.x; g.y += p.y; g.z += p.z; g.w += p.w;
    }
    float si = 1.f / (1.f + expf(-g.x));
    float sf = 1.f / (1.f + expf(-g.y));
    float so = 1.f / (1.f + expf(-g.w));
    float cn = sf * g_c[csrc][idx] + si * tanhf(g.z);
    float hn = so * tanhf(cn);
    g_c[cdst][idx] = cn;
    g_Hall[(size_t)t * Bc * DD + idx] = hn;
    if (t + 1 < TT)
        g_xcat[((size_t)(t + 1) * Bc + b) * KCAT + ED + ENC + d] = hn;
}

// ---------------- host launcher ----------------
extern "C" void kernel_launch(void* const* d_in, const int* in_sizes, int n_in,
                              void* d_out, int out_size)
{
    const float* features = (const float*)d_in[0];
    const int*   captions = (const int*)  d_in[1];
    const float* embedding= (const float*)d_in[2];
    const float* W_enc    = (const float*)d_in[3];
    const float* b_enc    = (const float*)d_in[4];
    const float* W_dec    = (const float*)d_in[5];
    const float* b_dec    = (const float*)d_in[6];
    const float* w_att    = (const float*)d_in[7];
    // d_in[8] b_att: softmax shift-invariant — dropped
    const float* Wi_h     = (const float*)d_in[9];
    const float* bi_h     = (const float*)d_in[10];
    const float* Wi_c     = (const float*)d_in[11];
    const float* bi_c     = (const float*)d_in[12];
    const float* W_ih     = (const float*)d_in[13];
    const float* b_ih     = (const float*)d_in[14];
    const float* W_hh     = (const float*)d_in[15];
    const float* b_hh     = (const float*)d_in[16];
    const float* W_out    = (const float*)d_in[17];
    const float* b_out    = (const float*)d_in[18];

    float* out = (float*)d_out;
    const size_t PRED_SZ = (size_t)Bc * TT * VV;
    float* alpha_out = ((size_t)out_size >= PRED_SZ + (size_t)Bc * TT * Nf)
                           ? (out + PRED_SZ) : nullptr;

    static float *p_featproj = nullptr, *p_Wcat, *p_meanf, *p_c,
                 *p_dppart, *p_xcat, *p_gpart, *p_Hall;
    if (!p_featproj) {
        cudaGetSymbolAddress((void**)&p_featproj, g_featproj_h);
        cudaGetSymbolAddress((void**)&p_Wcat,     g_Wcat);
        cudaGetSymbolAddress((void**)&p_meanf,    g_meanf);
        cudaGetSymbolAddress((void**)&p_c,        g_c);    // buffer 0
        cudaGetSymbolAddress((void**)&p_dppart,   g_dppart);
        cudaGetSymbolAddress((void**)&p_xcat,     g_xcat);
        cudaGetSymbolAddress((void**)&p_gpart,    g_gpart);
        cudaGetSymbolAddress((void**)&p_Hall,     g_Hall);
    }

    // ---- side stream + events (created outside capture; fallback if not) ----
    static cudaStream_t s2 = nullptr;
    static cudaEvent_t evF = nullptr, evM = nullptr, evW = nullptr,
                       evH = nullptr, evP = nullptr;
    static bool tried = false, streams_ok = false;
    if (!tried) {
        tried = true;
        cudaStreamCaptureStatus st = cudaStreamCaptureStatusNone;
        cudaStreamIsCapturing((cudaStream_t)0, &st);
        if (st == cudaStreamCaptureStatusNone) {
            bool ok = true;
            ok &= (cudaStreamCreateWithFlags(&s2, cudaStreamNonBlocking) == cudaSuccess);
            ok &= (cudaEventCreateWithFlags(&evF, cudaEventDisableTiming) == cudaSuccess);
            ok &= (cudaEventCreateWithFlags(&evM, cudaEventDisableTiming) == cudaSuccess);
            ok &= (cudaEventCreateWithFlags(&evW, cudaEventDisableTiming) == cudaSuccess);
            ok &= (cudaEventCreateWithFlags(&evH, cudaEventDisableTiming) == cudaSuccess);
            ok &= (cudaEventCreateWithFlags(&evP, cudaEventDisableTiming) == cudaSuccess);
            streams_ok = ok;
        }
    }
    const bool ovl = streams_ok;
    cudaStream_t S = (cudaStream_t)0;

    // ---- setup (fork: weights/emb/h0c0 on s2, meanf/featproj on main) ----
    if (ovl) cudaEventRecord(evF, S);

    meanf_kernel<<<(Bc * ENC + 255) / 256, 256, 0, S>>>(features);
    if (ovl) cudaEventRecord(evM, S);

    if (ovl) {
        cudaStreamWaitEvent(s2, evF, 0);
        wcat_kernel<<<(KCAT * G4 + 255) / 256, 256, 0, s2>>>(W_ih, W_hh, b_ih, b_hh);
        embfill_kernel<<<(TT * Bc * ED + 255) / 256, 256, 0, s2>>>(captions, embedding);
        cudaStreamWaitEvent(s2, evM, 0);
        dim3 grid(DD / 64, Bc / 32);
        gemm_f32<32, 64, 32, 4, 4><<<grid, 128, 0, s2>>>(
            p_meanf, ENC, Wi_h, DD, bi_h, p_xcat + ED + ENC, KCAT, Bc, DD, ENC);
        gemm_f32<32, 64, 32, 4, 4><<<grid, 128, 0, s2>>>(
            p_meanf, ENC, Wi_c, DD, bi_c, p_c, DD, Bc, DD, ENC);
        cudaEventRecord(evW, s2);
    } else {
        wcat_kernel<<<(KCAT * G4 + 255) / 256, 256, 0, S>>>(W_ih, W_hh, b_ih, b_hh);
        embfill_kernel<<<(TT * Bc * ED + 255) / 256, 256, 0, S>>>(captions, embedding);
        dim3 grid(DD / 64, Bc / 32);
        gemm_f32<32, 64, 32, 4, 4><<<grid, 128, 0, S>>>(
            p_meanf, ENC, Wi_h, DD, bi_h, p_xcat + ED + ENC, KCAT, Bc, DD, ENC);
        gemm_f32<32, 64, 32, 4, 4><<<grid, 128, 0, S>>>(
            p_meanf, ENC, Wi_c, DD, bi_c, p_c, DD, Bc, DD, ENC);
    }

    // feat_proj = features @ W_enc + b_enc  -> fp16 (main stream)
    {
        dim3 grid(AD / 128, (Bc * Nf) / 128);   // (4, 196)
        gemm_tc<0, true><<<grid, 256, 0, S>>>(features, ENC, W_enc, AD, b_enc,
                                              p_featproj, AD, Bc * Nf, AD, ENC, 0, 0);
    }
    if (ovl) cudaStreamWaitEvent(S, evW, 0);   // join: loop needs Wcat/emb/h0/c0

    // ---- serial step loop: 3 launches/step ----
    for (int t = 0; t < TT; t++) {
        // dec_proj (+ fused LSTM prologue for step t-1), tf32 split-K=8
        {
            dim3 grid(AD / 128, 1, DPS);        // (4,1,8)
            gemm_tc<6, false><<<grid, 256, 0, S>>>(
                p_xcat + (size_t)t * Bc * KCAT + ED + ENC, KCAT,
                W_dec, AD, nullptr, p_dppart, AD, Bc, AD, DD, DPCHUNK, t - 1);
        }

        if (ovl && t > 0 && (t % PBATCH == 0)) {
            // Hall[t-6 .. t-1] complete after dec_proj(t) prologue -> preds batch on s2
            int t0 = t - PBATCH;
            cudaEventRecord(evH, S);
            cudaStreamWaitEvent(s2, evH, 0);
            dim3 grid((VV + 127) / 128, PBATCH);   // (79,6)
            gemm_tc<1, false><<<grid, 256, 0, s2>>>(
                p_Hall + (size_t)t0 * Bc * DD, DD, W_out, VV, b_out,
                out, VV, PBATCH * Bc, VV, DD, 0, t0);
        }

        attn_kernel<<<Bc, 512, 0, S>>>(features, w_att, b_dec, alpha_out, t);

        // gates partials = xcat[t] @ Wcat  (tf32 split-K=8)
        {
            dim3 grid(G4 / 128, 1, KS);         // (16,1,8)
            gemm_tc<2, false><<<grid, 256, 0, S>>>(
                p_xcat + (size_t)t * Bc * KCAT, KCAT,
                p_Wcat, G4, nullptr, p_gpart, G4, Bc, G4, KCAT, GCHUNK, 0);
        }
    }
    // final LSTM (step TT-1) -> Hall[23]
    lstm_reduce<<<(Bc * DD + 255) / 256, 256, 0, S>>>(TT - 1);

    if (ovl) {
        // last preds batch [TT-6, TT-1]
        cudaEventRecord(evH, S);
        cudaStreamWaitEvent(s2, evH, 0);
        {
            int t0 = TT - PBATCH;
            dim3 grid((VV + 127) / 128, PBATCH);
            gemm_tc<1, false><<<grid, 256, 0, s2>>>(
                p_Hall + (size_t)t0 * Bc * DD, DD, W_out, VV, b_out,
                out, VV, PBATCH * Bc, VV, DD, 0, t0);
        }
        cudaEventRecord(evP, s2);
        cudaStreamWaitEvent(S, evP, 0);         // join before harness sync
    } else {
        // fallback: single preds GEMM with row remap
        dim3 grid((VV + 127) / 128, (TT * Bc) / 128);   // (79, 24)
        gemm_tc<1, false><<<grid, 256, 0, S>>>(p_Hall, DD, W_out, VV, b_out,
                                               out, VV, TT * Bc, VV, DD, 0, 0);
    }
}

// round 13
// speedup vs baseline: 1.3826x; 1.3826x over previous
#include <cuda_runtime.h>
#include <cuda_fp16.h>
#include <cstdint>

// ---------------- problem dims ----------------
constexpr int Bc   = 128;     // batch
constexpr int Nf   = 196;     // spatial features
constexpr int ENC  = 512;
constexpr int AD   = 512;     // attention dim
constexpr int DD   = 512;     // decoder dim
constexpr int ED   = 300;     // embed dim
constexpr int VV   = 10000;   // vocab
constexpr int LL   = 25;
constexpr int TT   = 24;      // L-1
constexpr int KCAT = ED + ENC + DD;   // 1324
constexpr int G4   = 4 * DD;          // 2048 (gate-interleaved: col = 4d+g)
constexpr int KS   = 8;               // split-K for gates GEMM
constexpr int GCHUNK = 168;           // 1324/8 rounded (mult of 4)
constexpr int DPS  = 4;               // split-K for dec_proj
constexpr int DPCHUNK = 128;
constexpr int PBATCH = 6;             // preds steps per side-stream batch

// ---------------- device scratch (static; no runtime alloc) ----------------
__device__ __half g_featproj_h[Bc * Nf * AD];     // 25.7 MB (fp16 feat_proj)
__device__ float g_Wcat[KCAT * G4];               // 10.9 MB (gate-interleaved col=4d+g)
__device__ float g_bcat[G4];
__device__ float g_meanf[Bc * ENC];
__device__ float g_c[Bc * DD];
__device__ float g_dppart[DPS * Bc * AD];         // dec_proj split-K partials
__device__ float g_xcat[TT * Bc * KCAT];          // 16.3 MB  [t][b][emb|ctx|h]
__device__ float g_gpart[KS * Bc * G4];           // 8 MB gates split-K partials
__device__ float g_Hall[TT * Bc * DD];            // 6.3 MB

// ---------------- PDL intrinsics (no-ops when kernel launched without PDL) -------
__device__ __forceinline__ void pdl_trigger() {
    asm volatile("griddepcontrol.launch_dependents;" ::: "memory");
}
__device__ __forceinline__ void pdl_wait() {
    asm volatile("griddepcontrol.wait;" ::: "memory");
}

// ================= TF32 tensor-core GEMM (unified) =================
// MODE 0: C[m*ldc+n] (+bias); OUTH: write __half
// MODE 1: m=t*128+b (t local) -> C[(b*TT + t0 + t)*ldc+n] + bias  (preds remap)
// MODE 2: split-K partial: K range [z*kchunk, ...), C += z*M*ldc, no bias
// PDL protocol: trigger at entry; B/bias loads (weights) before wait;
// A loads (predecessor output) and all global stores after wait.
__device__ __forceinline__ uint32_t f2tf(float x) {
    uint32_t r; asm("cvt.rna.tf32.f32 %0, %1;" : "=r"(r) : "f"(x)); return r;
}
__device__ __forceinline__ void mma8(float* c, const uint32_t* a, const uint32_t* b) {
    asm volatile("mma.sync.aligned.m16n8k8.row.col.f32.tf32.tf32.f32 "
                 "{%0,%1,%2,%3},{%4,%5,%6,%7},{%8,%9},{%0,%1,%2,%3};"
                 : "+f"(c[0]), "+f"(c[1]), "+f"(c[2]), "+f"(c[3])
                 : "r"(a[0]), "r"(a[1]), "r"(a[2]), "r"(a[3]), "r"(b[0]), "r"(b[1]));
}

template<int MODE, bool OUTH>
__global__ __launch_bounds__(256)
void gemm_tc(const float* __restrict__ A, int lda,
             const float* __restrict__ B, int ldb,
             const float* __restrict__ bias, float* __restrict__ C, int ldc,
             int M, int N, int K, int kchunk, int t0)
{
    pdl_trigger();   // let the dependent grid launch immediately

    constexpr int ASTR = 36;
    constexpr int BSTR = 136;
    __shared__ float As[128 * ASTR];   // [m][k]
    __shared__ float Bs[32 * BSTR];    // [k][n]

    const int tid  = threadIdx.x;
    const int lane = tid & 31, warp = tid >> 5;
    const int wm = (warp >> 2) * 64;
    const int wn = (warp & 3) * 32;
    const int l4 = lane >> 2, lq = lane & 3;
    const int row0 = blockIdx.y * 128;
    const int col0 = blockIdx.x * 128;
    const int kbeg = (MODE == 2) ? blockIdx.z * kchunk : 0;
    const int kend = (MODE == 2) ? min(K, kbeg + kchunk) : K;

    float acc[4][4][4];
#pragma unroll
    for (int i = 0; i < 4; i++)
#pragma unroll
        for (int j = 0; j < 4; j++)
#pragma unroll
            for (int q = 0; q < 4; q++) acc[i][j][q] = 0.f;

    const uint32_t* Asu = reinterpret_cast<const uint32_t*>(As);
    const uint32_t* Bsu = reinterpret_cast<const uint32_t*>(Bs);

    float4 pa[4], pb[4];
    auto ldA = [&](int kt) {
#pragma unroll
        for (int i = 0; i < 4; i++) {
            int l = tid + i * 256;
            int m = l >> 3, kq = (l & 7) << 2;
            int gk = kt + kq;
            pa[i] = make_float4(0.f, 0.f, 0.f, 0.f);
            if (gk < kend)
                pa[i] = *reinterpret_cast<const float4*>(A + (size_t)(row0 + m) * lda + gk);
        }
    };
    auto ldB = [&](int kt) {
#pragma unroll
        for (int i = 0; i < 4; i++) {
            int l = tid + i * 256;
            int k = l >> 5, nq = (l & 31) << 2;
            int gk = kt + k, gn = col0 + nq;
            pb[i] = make_float4(0.f, 0.f, 0.f, 0.f);
            if (gk < kend && gn < N)
                pb[i] = *reinterpret_cast<const float4*>(B + (size_t)gk * ldb + gn);
        }
    };

    ldB(kbeg);       // weights: independent of predecessor
    pdl_wait();      // predecessor's output (A) now complete + visible
    ldA(kbeg);
    for (int kt = kbeg; kt < kend; kt += 32) {
#pragma unroll
        for (int i = 0; i < 4; i++) {
            int l = tid + i * 256;
            int m = l >> 3, kq = (l & 7) << 2;
            uint4 u = make_uint4(f2tf(pa[i].x), f2tf(pa[i].y), f2tf(pa[i].z), f2tf(pa[i].w));
            *reinterpret_cast<uint4*>(As + m * ASTR + kq) = u;
        }
#pragma unroll
        for (int i = 0; i < 4; i++) {
            int l = tid + i * 256;
            int k = l >> 5, nq = (l & 31) << 2;
            uint4 u = make_uint4(f2tf(pb[i].x), f2tf(pb[i].y), f2tf(pb[i].z), f2tf(pb[i].w));
            *reinterpret_cast<uint4*>(Bs + k * BSTR + nq) = u;
        }
        __syncthreads();
        if (kt + 32 < kend) { ldA(kt + 32); ldB(kt + 32); }
#pragma unroll
        for (int kk = 0; kk < 32; kk += 8) {
            uint32_t af[4][4], bf[4][2];
#pragma unroll
            for (int mi = 0; mi < 4; mi++) {
                int r = wm + 16 * mi + l4;
                af[mi][0] = Asu[r * ASTR + kk + lq];
                af[mi][1] = Asu[(r + 8) * ASTR + kk + lq];
                af[mi][2] = Asu[r * ASTR + kk + lq + 4];
                af[mi][3] = Asu[(r + 8) * ASTR + kk + lq + 4];
            }
#pragma unroll
            for (int ni = 0; ni < 4; ni++) {
                int c = wn + 8 * ni + l4;
                bf[ni][0] = Bsu[(kk + lq) * BSTR + c];
                bf[ni][1] = Bsu[(kk + lq + 4) * BSTR + c];
            }
#pragma unroll
            for (int mi = 0; mi < 4; mi++)
#pragma unroll
                for (int ni = 0; ni < 4; ni++)
                    mma8(acc[mi][ni], af[mi], bf[ni]);
        }
        __syncthreads();
    }

    float* Cb = (MODE == 2) ? (C + (size_t)blockIdx.z * M * ldc) : C;
#pragma unroll
    for (int mi = 0; mi < 4; mi++) {
#pragma unroll
        for (int ni = 0; ni < 4; ni++) {
            int r = row0 + wm + 16 * mi + l4;
            int c = col0 + wn + 8 * ni + 2 * lq;
#pragma unroll
            for (int half = 0; half < 2; half++) {
                int rr = r + half * 8;
                size_t rowidx;
                if (MODE == 1) { int t = (rr >> 7) + t0, b = rr & 127; rowidx = (size_t)(b * TT + t); }
                else rowidx = (size_t)rr;
#pragma unroll
                for (int jj = 0; jj < 2; jj++) {
                    int cc = c + jj;
                    if (cc < N) {
                        float v = acc[mi][ni][half * 2 + jj];
                        if (MODE != 2 && bias) v += bias[cc];
                        if (OUTH)
                            reinterpret_cast<__half*>(Cb)[rowidx * ldc + cc] = __float2half_rn(v);
                        else
                            Cb[rowidx * ldc + cc] = v;
                    }
                }
            }
        }
    }
}

// ================= fp32 GEMM (h0/c0 only; exact, run once) =================
template<int BM, int BN, int BK, int TM, int TN>
__global__ void gemm_f32(const float* __restrict__ A, int lda,
                         const float* __restrict__ B, int ldb,
                         const float* __restrict__ bias, float* __restrict__ C, int ldc,
                         int M, int N, int K)
{
    constexpr int THREADS = (BM / TM) * (BN / TN);
    constexpr int AF4 = BM * BK / 4 / THREADS;
    constexpr int BF4 = BK * BN / 4 / THREADS;
    __shared__ float As[BK][BM];
    __shared__ float Bs[BK][BN];
    const int tid = threadIdx.x;
    const int tx = tid % (BN / TN), ty = tid / (BN / TN);
    const int row0 = blockIdx.y * BM, col0 = blockIdx.x * BN;

    float acc[TM][TN];
#pragma unroll
    for (int i = 0; i < TM; i++)
#pragma unroll
        for (int j = 0; j < TN; j++) acc[i][j] = 0.f;

    float4 pa[AF4], pb[BF4];
    auto load_regs = [&](int kt) {
#pragma unroll
        for (int i = 0; i < AF4; i++) {
            int l = tid + i * THREADS;
            int m = l / (BK / 4), kq = (l % (BK / 4)) * 4;
            pa[i] = *reinterpret_cast<const float4*>(A + (size_t)(row0 + m) * lda + kt + kq);
        }
#pragma unroll
        for (int i = 0; i < BF4; i++) {
            int l = tid + i * THREADS;
            int k = l / (BN / 4), nq = (l % (BN / 4)) * 4;
            pb[i] = *reinterpret_cast<const float4*>(B + (size_t)(kt + k) * ldb + col0 + nq);
        }
    };
    load_regs(0);
    for (int kt = 0; kt < K; kt += BK) {
#pragma unroll
        for (int i = 0; i < AF4; i++) {
            int l = tid + i * THREADS;
            int m = l / (BK / 4), kq = (l % (BK / 4)) * 4;
            As[kq + 0][m] = pa[i].x; As[kq + 1][m] = pa[i].y;
            As[kq + 2][m] = pa[i].z; As[kq + 3][m] = pa[i].w;
        }
#pragma unroll
        for (int i = 0; i < BF4; i++) {
            int l = tid + i * THREADS;
            int k = l / (BN / 4), nq = (l % (BN / 4)) * 4;
            *reinterpret_cast<float4*>(&Bs[k][nq]) = pb[i];
        }
        __syncthreads();
        if (kt + BK < K) load_regs(kt + BK);
#pragma unroll
        for (int kk = 0; kk < BK; kk++) {
            float ra[TM], rb[TN];
#pragma unroll
            for (int i = 0; i < TM; i += 4)
                *reinterpret_cast<float4*>(&ra[i]) =
                    *reinterpret_cast<const float4*>(&As[kk][ty * TM + i]);
#pragma unroll
            for (int j = 0; j < TN; j += 4)
                *reinterpret_cast<float4*>(&rb[j]) =
                    *reinterpret_cast<const float4*>(&Bs[kk][tx * TN + j]);
#pragma unroll
            for (int i = 0; i < TM; i++)
#pragma unroll
                for (int j = 0; j < TN; j++)
                    acc[i][j] = fmaf(ra[i], rb[j], acc[i][j]);
        }
        __syncthreads();
    }
#pragma unroll
    for (int i = 0; i < TM; i++) {
        int m = row0 + ty * TM + i;
#pragma unroll
        for (int j = 0; j < TN; j += 4) {
            int n = col0 + tx * TN + j;
            float4 v = make_float4(acc[i][j] + bias[n], acc[i][j + 1] + bias[n + 1],
                                   acc[i][j + 2] + bias[n + 2], acc[i][j + 3] + bias[n + 3]);
            *reinterpret_cast<float4*>(C + (size_t)m * ldc + n) = v;
        }
    }
}

// ---------------- setup kernels ----------------
__global__ void wcat_kernel(const float* __restrict__ Wih, const float* __restrict__ Whh,
                            const float* __restrict__ bih, const float* __restrict__ bhh)
{
    int idx = blockIdx.x * blockDim.x + threadIdx.x;
    if (idx >= KCAT * G4) return;
    int k = idx / G4, n = idx - k * G4;
    int d = n >> 2, g = n & 3;
    int col = g * DD + d;
    float v = (k < ED + ENC) ? Wih[(size_t)k * G4 + col]
                             : Whh[(size_t)(k - ED - ENC) * G4 + col];
    g_Wcat[idx] = v;
    if (idx < G4) {
        int dd = idx >> 2, gg = idx & 3;
        int c2 = gg * DD + dd;
        g_bcat[idx] = bih[c2] + bhh[c2];
    }
}

__global__ void meanf_kernel(const float* __restrict__ feat)
{
    int idx = blockIdx.x * blockDim.x + threadIdx.x;
    if (idx >= Bc * ENC) return;
    int b = idx >> 9, d = idx & 511;
    const float* p = feat + (size_t)b * Nf * ENC + d;
    float s = 0.f;
#pragma unroll 4
    for (int n = 0; n < Nf; n++) s += p[(size_t)n * ENC];
    g_meanf[idx] = s * (1.f / (float)Nf);
}

__global__ void embfill_kernel(const int* __restrict__ captions, const float* __restrict__ emb)
{
    int idx = blockIdx.x * blockDim.x + threadIdx.x;
    if (idx >= TT * Bc * ED) return;
    int t = idx / (Bc * ED);
    int r = idx - t * (Bc * ED);
    int b = r / ED, j = r - b * ED;
    int tok = captions[b * LL + t];
    g_xcat[((size_t)t * Bc + b) * KCAT + j] = emb[(size_t)tok * ED + j];
}

// ---------------- fused attention (dec_proj reduce + fp16 featproj + MUFU) ---------
__global__ __launch_bounds__(512)
void attn_kernel(const float* __restrict__ features, const float* __restrict__ w_att,
                 const float* __restrict__ b_dec, float* __restrict__ alpha_out, int t)
{
    pdl_trigger();
    __shared__ float decp[AD];
    __shared__ float watt[AD];
    __shared__ float al[Nf];
    __shared__ float red[256];
    const int b = blockIdx.x, tid = threadIdx.x;
    watt[tid] = w_att[tid];            // weights: independent of predecessor
    float bd = b_dec[tid];
    pdl_wait();                        // dec_proj partials ready
    {
        float s = bd;
#pragma unroll
        for (int z = 0; z < DPS; z++)
            s += g_dppart[((size_t)z * Bc + b) * AD + tid];
        decp[tid] = s;
    }
    __syncthreads();

    const int warp = tid >> 5, lane = tid & 31;
    for (int n = warp; n < Nf; n += 16) {
        const __half* fp = g_featproj_h + ((size_t)b * Nf + n) * AD;
        float s = 0.f;
#pragma unroll
        for (int a = lane * 2; a < AD; a += 64) {
            __half2 h2 = *reinterpret_cast<const __half2*>(fp + a);
            float2 f2 = __half22float2(h2);
            float t0, t1;
            asm("tanh.approx.f32 %0, %1;" : "=f"(t0) : "f"(f2.x + decp[a]));
            asm("tanh.approx.f32 %0, %1;" : "=f"(t1) : "f"(f2.y + decp[a + 1]));
            s += t0 * watt[a] + t1 * watt[a + 1];
        }
#pragma unroll
        for (int o = 16; o; o >>= 1) s += __shfl_xor_sync(0xFFFFFFFFu, s, o);
        if (lane == 0) al[n] = s;
    }
    __syncthreads();

    if (tid < 256) red[tid] = (tid < Nf) ? al[tid] : -1e30f;
    __syncthreads();
    for (int s = 128; s; s >>= 1) { if (tid < s) red[tid] = fmaxf(red[tid], red[tid + s]); __syncthreads(); }
    float mx = red[0];
    __syncthreads();
    float e = (tid < Nf) ? __expf(al[tid] - mx) : 0.f;
    if (tid < 256) red[tid] = e;
    __syncthreads();
    for (int s = 128; s; s >>= 1) { if (tid < s) red[tid] += red[tid + s]; __syncthreads(); }
    float inv = 1.f / red[0];
    if (tid < Nf) {
        float a = e * inv;
        al[tid] = a;
        if (alpha_out) alpha_out[(size_t)(b * TT + t) * Nf + tid] = a;
    }
    __syncthreads();

    const float* fb = features + (size_t)b * Nf * ENC;
    float s = 0.f;
#pragma unroll 4
    for (int n = 0; n < Nf; n++) s += al[n] * fb[(size_t)n * ENC + tid];
    g_xcat[((size_t)t * Bc + b) * KCAT + ED + tid] = s;
}

// ---------------- split-K reduce + LSTM pointwise ----------------
__global__ void lstm_reduce(int t)
{
    pdl_trigger();
    int idx = blockIdx.x * blockDim.x + threadIdx.x;
    if (idx >= Bc * DD) { pdl_wait(); return; }
    int b = idx >> 9, d = idx & 511;
    float4 g = reinterpret_cast<const float4*>(g_bcat)[d];   // setup data: safe
    pdl_wait();                                              // gates partials ready
    const float4* gp = reinterpret_cast<const float4*>(g_gpart);
#pragma unroll
    for (int ks = 0; ks < KS; ks++) {
        float4 p = gp[((size_t)(ks * Bc + b) * G4 >> 2) + d];
        g.x += p.x; g.y += p.y; g.z += p.z; g.w += p.w;
    }
    float si = 1.f / (1.f + expf(-g.x));
    float sf = 1.f / (1.f + expf(-g.y));
    float so = 1.f / (1.f + expf(-g.w));
    float cn = sf * g_c[idx] + si * tanhf(g.z);
    float hn = so * tanhf(cn);
    g_c[idx] = cn;
    g_Hall[(size_t)t * Bc * DD + idx] = hn;
    if (t + 1 < TT)
        g_xcat[((size_t)(t + 1) * Bc + b) * KCAT + ED + ENC + d] = hn;
}

// ---------------- PDL launch helper (falls back to plain launch) ----------------
template<typename Kern, typename... Args>
static inline void launch_pdl(Kern kern, dim3 grid, dim3 block, cudaStream_t s, Args... args)
{
    cudaLaunchConfig_t cfg = {};
    cfg.gridDim = grid; cfg.blockDim = block;
    cfg.dynamicSmemBytes = 0; cfg.stream = s;
    cudaLaunchAttribute attr[1];
    attr[0].id = cudaLaunchAttributeProgrammaticStreamSerialization;
    attr[0].val.programmaticStreamSerializationAllowed = 1;
    cfg.attrs = attr; cfg.numAttrs = 1;
    if (cudaLaunchKernelEx(&cfg, kern, args...) != cudaSuccess)
        kern<<<grid, block, 0, s>>>(args...);
}

// ---------------- host launcher ----------------
extern "C" void kernel_launch(void* const* d_in, const int* in_sizes, int n_in,
                              void* d_out, int out_size)
{
    const float* features = (const float*)d_in[0];
    const int*   captions = (const int*)  d_in[1];
    const float* embedding= (const float*)d_in[2];
    const float* W_enc    = (const float*)d_in[3];
    const float* b_enc    = (const float*)d_in[4];
    const float* W_dec    = (const float*)d_in[5];
    const float* b_dec    = (const float*)d_in[6];
    const float* w_att    = (const float*)d_in[7];
    // d_in[8] b_att: softmax shift-invariant — dropped
    const float* Wi_h     = (const float*)d_in[9];
    const float* bi_h     = (const float*)d_in[10];
    const float* Wi_c     = (const float*)d_in[11];
    const float* bi_c     = (const float*)d_in[12];
    const float* W_ih     = (const float*)d_in[13];
    const float* b_ih     = (const float*)d_in[14];
    const float* W_hh     = (const float*)d_in[15];
    const float* b_hh     = (const float*)d_in[16];
    const float* W_out    = (const float*)d_in[17];
    const float* b_out    = (const float*)d_in[18];

    float* out = (float*)d_out;
    const size_t PRED_SZ = (size_t)Bc * TT * VV;
    float* alpha_out = ((size_t)out_size >= PRED_SZ + (size_t)Bc * TT * Nf)
                           ? (out + PRED_SZ) : nullptr;

    static float *p_featproj = nullptr, *p_Wcat, *p_meanf, *p_c,
                 *p_dppart, *p_xcat, *p_gpart, *p_Hall;
    if (!p_featproj) {
        cudaGetSymbolAddress((void**)&p_featproj, g_featproj_h);
        cudaGetSymbolAddress((void**)&p_Wcat,     g_Wcat);
        cudaGetSymbolAddress((void**)&p_meanf,    g_meanf);
        cudaGetSymbolAddress((void**)&p_c,        g_c);
        cudaGetSymbolAddress((void**)&p_dppart,   g_dppart);
        cudaGetSymbolAddress((void**)&p_xcat,     g_xcat);
        cudaGetSymbolAddress((void**)&p_gpart,    g_gpart);
        cudaGetSymbolAddress((void**)&p_Hall,     g_Hall);
    }

    // ---- side stream + events (created outside capture; fallback if not) ----
    static cudaStream_t s2 = nullptr;
    static cudaEvent_t evF = nullptr, evM = nullptr, evW = nullptr,
                       evH = nullptr, evP = nullptr;
    static bool tried = false, streams_ok = false;
    if (!tried) {
        tried = true;
        cudaStreamCaptureStatus st = cudaStreamCaptureStatusNone;
        cudaStreamIsCapturing((cudaStream_t)0, &st);
        if (st == cudaStreamCaptureStatusNone) {
            bool ok = true;
            ok &= (cudaStreamCreateWithFlags(&s2, cudaStreamNonBlocking) == cudaSuccess);
            ok &= (cudaEventCreateWithFlags(&evF, cudaEventDisableTiming) == cudaSuccess);
            ok &= (cudaEventCreateWithFlags(&evM, cudaEventDisableTiming) == cudaSuccess);
            ok &= (cudaEventCreateWithFlags(&evW, cudaEventDisableTiming) == cudaSuccess);
            ok &= (cudaEventCreateWithFlags(&evH, cudaEventDisableTiming) == cudaSuccess);
            ok &= (cudaEventCreateWithFlags(&evP, cudaEventDisableTiming) == cudaSuccess);
            streams_ok = ok;
        }
    }
    const bool ovl = streams_ok;
    cudaStream_t S = (cudaStream_t)0;

    // ---- setup (fork: weights/emb/h0c0 on s2, meanf/featproj on main) ----
    if (ovl) cudaEventRecord(evF, S);

    meanf_kernel<<<(Bc * ENC + 255) / 256, 256, 0, S>>>(features);
    if (ovl) cudaEventRecord(evM, S);

    if (ovl) {
        cudaStreamWaitEvent(s2, evF, 0);
        wcat_kernel<<<(KCAT * G4 + 255) / 256, 256, 0, s2>>>(W_ih, W_hh, b_ih, b_hh);
        embfill_kernel<<<(TT * Bc * ED + 255) / 256, 256, 0, s2>>>(captions, embedding);
        cudaStreamWaitEvent(s2, evM, 0);
        dim3 grid(DD / 64, Bc / 32);
        gemm_f32<32, 64, 32, 4, 4><<<grid, 128, 0, s2>>>(
            p_meanf, ENC, Wi_h, DD, bi_h, p_xcat + ED + ENC, KCAT, Bc, DD, ENC);
        gemm_f32<32, 64, 32, 4, 4><<<grid, 128, 0, s2>>>(
            p_meanf, ENC, Wi_c, DD, bi_c, p_c, DD, Bc, DD, ENC);
        cudaEventRecord(evW, s2);
    } else {
        wcat_kernel<<<(KCAT * G4 + 255) / 256, 256, 0, S>>>(W_ih, W_hh, b_ih, b_hh);
        embfill_kernel<<<(TT * Bc * ED + 255) / 256, 256, 0, S>>>(captions, embedding);
        dim3 grid(DD / 64, Bc / 32);
        gemm_f32<32, 64, 32, 4, 4><<<grid, 128, 0, S>>>(
            p_meanf, ENC, Wi_h, DD, bi_h, p_xcat + ED + ENC, KCAT, Bc, DD, ENC);
        gemm_f32<32, 64, 32, 4, 4><<<grid, 128, 0, S>>>(
            p_meanf, ENC, Wi_c, DD, bi_c, p_c, DD, Bc, DD, ENC);
    }

    // feat_proj = features @ W_enc + b_enc  -> fp16 (main stream, plain launch)
    {
        dim3 grid(AD / 128, (Bc * Nf) / 128);   // (4, 196)
        gemm_tc<0, true><<<grid, 256, 0, S>>>(features, ENC, W_enc, AD, b_enc,
                                              p_featproj, AD, Bc * Nf, AD, ENC, 0, 0);
    }
    if (ovl) cudaStreamWaitEvent(S, evW, 0);   // join: loop needs Wcat/emb/h0/c0

    // ---- serial step loop: 4 PDL-chained launches/step ----
    for (int t = 0; t < TT; t++) {
        // dec_proj partials = h_t @ W_dec  (tf32 split-K=4; reduced in attn)
        launch_pdl(gemm_tc<2, false>, dim3(AD / 128, 1, DPS), dim3(256), S,
                   (const float*)(p_xcat + (size_t)t * Bc * KCAT + ED + ENC), KCAT,
                   W_dec, AD, (const float*)nullptr, p_dppart, AD,
                   Bc, AD, DD, DPCHUNK, 0);

        launch_pdl(attn_kernel, dim3(Bc), dim3(512), S,
                   features, w_att, b_dec, alpha_out, t);

        // gates partials = xcat[t] @ Wcat  (tf32 split-K=8)
        launch_pdl(gemm_tc<2, false>, dim3(G4 / 128, 1, KS), dim3(256), S,
                   (const float*)(p_xcat + (size_t)t * Bc * KCAT), KCAT,
                   (const float*)p_Wcat, G4, (const float*)nullptr, p_gpart, G4,
                   Bc, G4, KCAT, GCHUNK, 0);

        launch_pdl(lstm_reduce, dim3((Bc * DD + 255) / 256), dim3(256), S, t);

        if (ovl && (t % PBATCH == PBATCH - 1)) {
            // preds for steps [t-5, t] in one fat GEMM on side stream
            int t0 = t - (PBATCH - 1);
            cudaEventRecord(evH, S);
            cudaStreamWaitEvent(s2, evH, 0);
            dim3 grid((VV + 127) / 128, PBATCH);   // (79,6)
            gemm_tc<1, false><<<grid, 256, 0, s2>>>(
                p_Hall + (size_t)t0 * Bc * DD, DD, W_out, VV, b_out,
                out, VV, PBATCH * Bc, VV, DD, 0, t0);
        }
    }

    if (ovl) {
        cudaEventRecord(evP, s2);
        cudaStreamWaitEvent(S, evP, 0);         // join before harness sync
    } else {
        // fallback: single preds GEMM with row remap
        dim3 grid((VV + 127) / 128, (TT * Bc) / 128);   // (79, 24)
        gemm_tc<1, false><<<grid, 256, 0, S>>>(p_Hall, DD, W_out, VV, b_out,
                                               out, VV, TT * Bc, VV, DD, 0, 0);
    }
}